// round 3
// baseline (speedup 1.0000x reference)
#include <cuda_runtime.h>
#include <math.h>

// ---------------- problem constants ----------------
#define TS     2048          // tokens (S*B)
#define HDIM   1024
#define NHEADS 16
#define HEADD  64
#define NEXP   8
#define FF     2048
#define NSLOTS (2 * TS)      // exactly top-2 assignments total

// ---------------- scratch (static device globals; no allocation) ----------------
__device__ float g_hn   [TS * HDIM];
__device__ float g_qkv  [TS * 3 * HDIM];
__device__ float g_attn [TS * HDIM];
__device__ float g_x1   [TS * HDIM];
__device__ float g_hn2  [TS * HDIM];
__device__ float g_logits[TS * NEXP];
__device__ float g_gate [TS * 2];
__device__ int   g_topi [TS * 2];
__device__ int   g_cnt  [NEXP];
__device__ int   g_off  [NEXP];            // exclusive prefix of g_cnt
__device__ int   g_etok [NEXP * TS];
__device__ float g_egate[NEXP * TS];
__device__ float g_hmid [NSLOTS * FF];     // compact: [g_off[e]+pos][F]  (32 MB)

// ---------------- LayerNorm: one block per token ----------------
__global__ void ln_kernel(const float* __restrict__ x, const float* __restrict__ w,
                          const float* __restrict__ b, float* __restrict__ out) {
    int t = blockIdx.x, tid = threadIdx.x;
    const float* row = x + t * HDIM;
    __shared__ float red[256];

    float s = 0.f;
    for (int i = tid; i < HDIM; i += 256) s += row[i];
    red[tid] = s; __syncthreads();
    for (int off = 128; off > 0; off >>= 1) { if (tid < off) red[tid] += red[tid + off]; __syncthreads(); }
    float mu = red[0] * (1.f / HDIM);
    __syncthreads();

    float v = 0.f;
    for (int i = tid; i < HDIM; i += 256) { float d = row[i] - mu; v += d * d; }
    red[tid] = v; __syncthreads();
    for (int off = 128; off > 0; off >>= 1) { if (tid < off) red[tid] += red[tid + off]; __syncthreads(); }
    float rs = rsqrtf(red[0] * (1.f / HDIM) + 1e-5f);

    for (int i = tid; i < HDIM; i += 256)
        out[t * HDIM + i] = (row[i] - mu) * rs * w[i] + b[i];
}

// ---------------- generic fp32 GEMM: C[M,N] = A[M,K] * B[N,K]^T (+bias +resid) ----------------
// BM=BN=64, BK=16, 256 threads, each thread 4x4.
__global__ void gemm_tn_kernel(const float* __restrict__ A, const float* __restrict__ Bm,
                               const float* __restrict__ bias, const float* __restrict__ resid,
                               float* __restrict__ C, int M, int N, int K) {
    __shared__ float As[16][64];
    __shared__ float Bs[16][64];
    int tid = threadIdx.x;
    int m0 = blockIdx.y * 64, n0 = blockIdx.x * 64;
    int am = tid >> 2, ak = (tid & 3) << 2;     // loader: row am, 4 k's
    int tx = tid & 15, ty = tid >> 4;           // compute: rows ty*4.., cols tx*4..
    float acc[4][4] = {};

    const float* Ap = A  + (long)(m0 + am) * K + ak;
    const float* Bp = Bm + (long)(n0 + am) * K + ak;

    for (int k0 = 0; k0 < K; k0 += 16) {
        float4 a = *(const float4*)(Ap + k0);
        float4 b = *(const float4*)(Bp + k0);
        As[ak+0][am] = a.x; As[ak+1][am] = a.y; As[ak+2][am] = a.z; As[ak+3][am] = a.w;
        Bs[ak+0][am] = b.x; Bs[ak+1][am] = b.y; Bs[ak+2][am] = b.z; Bs[ak+3][am] = b.w;
        __syncthreads();
        #pragma unroll
        for (int k = 0; k < 16; k++) {
            float4 av = *(const float4*)&As[k][ty << 2];
            float4 bv = *(const float4*)&Bs[k][tx << 2];
            float aa[4] = {av.x, av.y, av.z, av.w};
            float bb[4] = {bv.x, bv.y, bv.z, bv.w};
            #pragma unroll
            for (int i = 0; i < 4; i++)
                #pragma unroll
                for (int j = 0; j < 4; j++)
                    acc[i][j] += aa[i] * bb[j];
        }
        __syncthreads();
    }

    #pragma unroll
    for (int i = 0; i < 4; i++) {
        int m = m0 + (ty << 2) + i;
        #pragma unroll
        for (int j = 0; j < 4; j++) {
            int n = n0 + (tx << 2) + j;
            float v = acc[i][j];
            if (bias)  v += bias[n];
            if (resid) v += resid[(long)m * N + n];
            C[(long)m * N + n] = v;
        }
    }
}

// ---------------- flash attention: 64 queries per block, 64 threads ----------------
// dyn smem: Qs[64*64] | Ks[64*64] | Vs[64*64] | Ps[64*65] = 65792 bytes
__global__ void attn_kernel(const float* __restrict__ qkv, float* __restrict__ aout) {
    extern __shared__ float sm[];
    float* Qs = sm;
    float* Ks = sm + 4096;
    float* Vs = sm + 8192;
    float* Ps = sm + 12288;

    int h = blockIdx.y;
    int m0 = blockIdx.x * 64;
    int tid = threadIdx.x;
    int qrow = m0 + tid;

    // stage Q tile into smem as Qs[d][row]
    for (int r = 0; r < 64; r++)
        Qs[tid * 64 + r] = qkv[(long)(m0 + r) * 3 * HDIM + h * HEADD + tid];
    __syncthreads();

    float o[64];
    #pragma unroll
    for (int d = 0; d < 64; d++) o[d] = 0.f;
    float mx = -1e30f, l = 0.f;

    for (int j = 0; j <= (int)blockIdx.x; j++) {
        int n0 = j * 64;
        __syncthreads();
        for (int r = 0; r < 64; r++) {
            Ks[r * 64 + tid] = qkv[(long)(n0 + r) * 3 * HDIM + HDIM   + h * HEADD + tid];
            Vs[r * 64 + tid] = qkv[(long)(n0 + r) * 3 * HDIM + 2*HDIM + h * HEADD + tid];
        }
        __syncthreads();

        float tmax = mx;
        for (int c = 0; c < 64; c++) {
            float s = 0.f;
            #pragma unroll
            for (int d = 0; d < 64; d++) s += Qs[d * 64 + tid] * Ks[c * 64 + d];
            s *= 0.125f;                      // 1/sqrt(64)
            if (n0 + c > qrow) s = -1e30f;    // causal mask
            Ps[tid * 65 + c] = s;
            tmax = fmaxf(tmax, s);
        }
        float scale = __expf(mx - tmax);
        l *= scale;
        #pragma unroll
        for (int d = 0; d < 64; d++) o[d] *= scale;
        for (int c = 0; c < 64; c++) {
            float p = __expf(Ps[tid * 65 + c] - tmax);
            l += p;
            Ps[tid * 65 + c] = p;
        }
        mx = tmax;
        for (int c = 0; c < 64; c++) {
            float p = Ps[tid * 65 + c];
            #pragma unroll
            for (int d = 0; d < 64; d++) o[d] += p * Vs[c * 64 + d];
        }
    }

    float inv = 1.f / l;
    float* op = &aout[(long)qrow * HDIM + h * HEADD];
    #pragma unroll
    for (int d = 0; d < 64; d++) op[d] = o[d] * inv;
}

// ---------------- router logits: block per token, warp per expert ----------------
__global__ void router_kernel(const float* __restrict__ rw) {
    int t = blockIdx.x;
    int e = threadIdx.x >> 5, lane = threadIdx.x & 31;
    float s = 0.f;
    for (int i = lane; i < HDIM; i += 32)
        s += g_hn2[(long)t * HDIM + i] * rw[(long)e * HDIM + i];
    #pragma unroll
    for (int off = 16; off > 0; off >>= 1) s += __shfl_down_sync(0xffffffffu, s, off);
    if (lane == 0) g_logits[t * NEXP + e] = s;
}

// ---------------- softmax + top-2 per token ----------------
__global__ void top2_kernel() {
    int t = blockIdx.x * blockDim.x + threadIdx.x;
    if (t >= TS) return;
    float l[NEXP];
    float m = -1e30f;
    #pragma unroll
    for (int e = 0; e < NEXP; e++) { l[e] = g_logits[t * NEXP + e]; m = fmaxf(m, l[e]); }
    float sum = 0.f;
    #pragma unroll
    for (int e = 0; e < NEXP; e++) { l[e] = __expf(l[e] - m); sum += l[e]; }
    int i1 = 0;
    #pragma unroll
    for (int e = 1; e < NEXP; e++) if (l[e] > l[i1]) i1 = e;
    int i2 = (i1 == 0) ? 1 : 0;
    #pragma unroll
    for (int e = 0; e < NEXP; e++) if (e != i1 && l[e] > l[i2]) i2 = e;
    float inv = 1.f / sum;
    g_topi[2*t]   = i1;  g_gate[2*t]   = l[i1] * inv;
    g_topi[2*t+1] = i2;  g_gate[2*t+1] = l[i2] * inv;
}

// ---------------- deterministic per-expert token lists (block scan, no atomics) ----------------
__global__ void build_lists_kernel() {
    int e = blockIdx.x, tid = threadIdx.x;
    __shared__ int sc[256];
    __shared__ int sbase;
    if (tid == 0) sbase = 0;
    __syncthreads();
    for (int t0 = 0; t0 < TS; t0 += 256) {
        int t = t0 + tid;
        int flag = 0; float g = 0.f;
        int i0 = g_topi[2*t], i1 = g_topi[2*t+1];
        if (i0 == e)      { flag = 1; g = g_gate[2*t]; }
        else if (i1 == e) { flag = 1; g = g_gate[2*t+1]; }
        sc[tid] = flag;
        __syncthreads();
        for (int off = 1; off < 256; off <<= 1) {    // Hillis-Steele inclusive scan
            int v = (tid >= off) ? sc[tid - off] : 0;
            __syncthreads();
            sc[tid] += v;
            __syncthreads();
        }
        if (flag) {
            int pos = sbase + sc[tid] - 1;
            g_etok [e * TS + pos] = t;
            g_egate[e * TS + pos] = g;
        }
        __syncthreads();
        if (tid == 0) sbase += sc[255];
        __syncthreads();
    }
    if (tid == 0) g_cnt[e] = sbase;
}

// ---------------- exclusive scan of expert counts -> g_off ----------------
__global__ void scan_offsets_kernel() {
    if (threadIdx.x == 0) {
        int acc = 0;
        for (int e = 0; e < NEXP; e++) { g_off[e] = acc; acc += g_cnt[e]; }
    }
}

// ---------------- out = x1 (residual base for MoE scatter-add) ----------------
__global__ void copy_kernel(float* __restrict__ out) {
    int i = blockIdx.x * blockDim.x + threadIdx.x;
    out[i] = g_x1[i];
}

// ---------------- MoE GEMM1: hmid[off[e]+m,:] = gelu( hn2[tok] @ w1[e] )  (w1 is [K=H][N=F]) ----------------
__global__ void moe_gemm1_kernel(const float* __restrict__ w1) {
    int e = blockIdx.z;
    int cnt = g_cnt[e];
    int m0 = blockIdx.y * 64;
    if (m0 >= cnt) return;
    int base = g_off[e];
    int n0 = blockIdx.x * 64;

    __shared__ float As[16][64];
    __shared__ float Bs[16][64];
    __shared__ int toks[64];
    int tid = threadIdx.x;
    if (tid < 64) {
        int m = m0 + tid;
        toks[tid] = g_etok[e * TS + (m < cnt ? m : cnt - 1)];
    }
    __syncthreads();

    const float* B = w1 + (long)e * HDIM * FF;
    int am = tid >> 2, ak = (tid & 3) << 2;
    int bk = tid >> 4, bn = (tid & 15) << 2;
    int tx = tid & 15, ty = tid >> 4;
    float acc[4][4] = {};

    for (int k0 = 0; k0 < HDIM; k0 += 16) {
        float4 a  = *(const float4*)&g_hn2[(long)toks[am] * HDIM + k0 + ak];
        float4 b4 = *(const float4*)&B[(long)(k0 + bk) * FF + n0 + bn];
        As[ak+0][am] = a.x; As[ak+1][am] = a.y; As[ak+2][am] = a.z; As[ak+3][am] = a.w;
        *(float4*)&Bs[bk][bn] = b4;
        __syncthreads();
        #pragma unroll
        for (int k = 0; k < 16; k++) {
            float4 av = *(const float4*)&As[k][ty << 2];
            float4 bv = *(const float4*)&Bs[k][tx << 2];
            float aa[4] = {av.x, av.y, av.z, av.w};
            float bb[4] = {bv.x, bv.y, bv.z, bv.w};
            #pragma unroll
            for (int i = 0; i < 4; i++)
                #pragma unroll
                for (int j = 0; j < 4; j++)
                    acc[i][j] += aa[i] * bb[j];
        }
        __syncthreads();
    }

    #pragma unroll
    for (int i = 0; i < 4; i++) {
        int row = (ty << 2) + i;
        if (m0 + row < cnt) {
            #pragma unroll
            for (int j = 0; j < 4; j++) {
                float v = acc[i][j];
                float gl = 0.5f * v * (1.f + erff(v * 0.70710678118654752f));  // exact GELU
                g_hmid[(long)(base + m0 + row) * FF + n0 + (tx << 2) + j] = gl;
            }
        }
    }
}

// ---------------- MoE GEMM2: out[tok] += gate * ( hmid[off[e]+m,:] @ w2[e] )  (w2 is [K=F][N=H]) ----------------
__global__ void moe_gemm2_kernel(const float* __restrict__ w2, float* __restrict__ out) {
    int e = blockIdx.z;
    int cnt = g_cnt[e];
    int m0 = blockIdx.y * 64;
    if (m0 >= cnt) return;
    int base = g_off[e];
    int n0 = blockIdx.x * 64;

    __shared__ float As[16][64];
    __shared__ float Bs[16][64];
    __shared__ int   toks[64];
    __shared__ float gts[64];
    int tid = threadIdx.x;
    if (tid < 64) {
        int m = m0 + tid;
        int mc = (m < cnt ? m : cnt - 1);
        toks[tid] = g_etok [e * TS + mc];
        gts [tid] = g_egate[e * TS + mc];
    }
    __syncthreads();

    const float* A = g_hmid + (long)base * FF;
    const float* B = w2 + (long)e * FF * HDIM;
    int am = tid >> 2, ak = (tid & 3) << 2;
    int bk = tid >> 4, bn = (tid & 15) << 2;
    int tx = tid & 15, ty = tid >> 4;
    float acc[4][4] = {};

    for (int k0 = 0; k0 < FF; k0 += 16) {
        float4 a  = *(const float4*)&A[(long)(m0 + am) * FF + k0 + ak];
        float4 b4 = *(const float4*)&B[(long)(k0 + bk) * HDIM + n0 + bn];
        As[ak+0][am] = a.x; As[ak+1][am] = a.y; As[ak+2][am] = a.z; As[ak+3][am] = a.w;
        *(float4*)&Bs[bk][bn] = b4;
        __syncthreads();
        #pragma unroll
        for (int k = 0; k < 16; k++) {
            float4 av = *(const float4*)&As[k][ty << 2];
            float4 bv = *(const float4*)&Bs[k][tx << 2];
            float aa[4] = {av.x, av.y, av.z, av.w};
            float bb[4] = {bv.x, bv.y, bv.z, bv.w};
            #pragma unroll
            for (int i = 0; i < 4; i++)
                #pragma unroll
                for (int j = 0; j < 4; j++)
                    acc[i][j] += aa[i] * bb[j];
        }
        __syncthreads();
    }

    #pragma unroll
    for (int i = 0; i < 4; i++) {
        int row = (ty << 2) + i;
        if (m0 + row < cnt) {
            int tok = toks[row];
            float gg = gts[row];
            #pragma unroll
            for (int j = 0; j < 4; j++)
                atomicAdd(&out[(long)tok * HDIM + n0 + (tx << 2) + j], gg * acc[i][j]);
        }
    }
}

// ---------------- launch ----------------
extern "C" void kernel_launch(void* const* d_in, const int* in_sizes, int n_in,
                              void* d_out, int out_size) {
    const float* x    = (const float*)d_in[0];
    const float* ln1w = (const float*)d_in[1];
    const float* ln1b = (const float*)d_in[2];
    const float* wqkv = (const float*)d_in[3];
    const float* bqkv = (const float*)d_in[4];
    const float* wout = (const float*)d_in[5];
    const float* bout = (const float*)d_in[6];
    const float* ln2w = (const float*)d_in[7];
    const float* ln2b = (const float*)d_in[8];
    const float* rw   = (const float*)d_in[9];
    const float* w1   = (const float*)d_in[10];
    const float* w2   = (const float*)d_in[11];
    float* out = (float*)d_out;

    float *p_hn, *p_qkv, *p_attn, *p_x1, *p_hn2;
    cudaGetSymbolAddress((void**)&p_hn,   g_hn);
    cudaGetSymbolAddress((void**)&p_qkv,  g_qkv);
    cudaGetSymbolAddress((void**)&p_attn, g_attn);
    cudaGetSymbolAddress((void**)&p_x1,   g_x1);
    cudaGetSymbolAddress((void**)&p_hn2,  g_hn2);

    cudaFuncSetAttribute(attn_kernel, cudaFuncAttributeMaxDynamicSharedMemorySize, 65792);

    // 1) LN1
    ln_kernel<<<TS, 256>>>(x, ln1w, ln1b, p_hn);
    // 2) QKV projection
    {
        dim3 g(3 * HDIM / 64, TS / 64);
        gemm_tn_kernel<<<g, 256>>>(p_hn, wqkv, bqkv, nullptr, p_qkv, TS, 3 * HDIM, HDIM);
    }
    // 3) causal attention
    {
        dim3 g(TS / 64, NHEADS);
        attn_kernel<<<g, 64, 65792>>>(p_qkv, p_attn);
    }
    // 4) out projection + residual -> x1
    {
        dim3 g(HDIM / 64, TS / 64);
        gemm_tn_kernel<<<g, 256>>>(p_attn, wout, bout, x, p_x1, TS, HDIM, HDIM);
    }
    // 5) LN2
    ln_kernel<<<TS, 256>>>(p_x1, ln2w, ln2b, p_hn2);
    // 6) router + top-2 + deterministic expert lists + offsets
    router_kernel<<<TS, 256>>>(rw);
    top2_kernel<<<TS / 256, 256>>>();
    build_lists_kernel<<<NEXP, 256>>>();
    scan_offsets_kernel<<<1, 32>>>();
    // 7) out = x1
    copy_kernel<<<TS * HDIM / 256, 256>>>(out);
    // 8) MoE expert GEMMs (sparse top-2)
    {
        dim3 g1(FF / 64, TS / 64, NEXP);
        moe_gemm1_kernel<<<g1, 256>>>(w1);
        dim3 g2(HDIM / 64, TS / 64, NEXP);
        moe_gemm2_kernel<<<g2, 256>>>(w2, out);
    }
}

// round 6
// speedup vs baseline: 1.1142x; 1.1142x over previous
#include <cuda_runtime.h>
#include <math.h>
#include <stdint.h>

// ---------------- problem constants ----------------
#define TS     2048          // tokens (S*B)
#define HDIM   1024
#define NHEADS 16
#define HEADD  64
#define NEXP   8
#define FF     2048
#define NSLOTS (2 * TS)      // exactly top-2 assignments total

// ---------------- scratch (static device globals; no allocation) ----------------
__device__ float g_hn   [TS * HDIM];
__device__ float g_qkv  [TS * 3 * HDIM];
__device__ float g_attn [TS * HDIM];
__device__ float g_x1   [TS * HDIM];
__device__ float g_hn2  [TS * HDIM];
__device__ float g_logits[TS * NEXP];
__device__ float g_gate [TS * 2];
__device__ int   g_topi [TS * 2];
__device__ int   g_cnt  [NEXP];
__device__ int   g_off  [NEXP];
__device__ int   g_etok [NEXP * TS];
__device__ float g_egate[NEXP * TS];
__device__ float g_hmid [(NSLOTS + 64) * FF];  // +64 rows padding for tile overhang

// ---------------- LayerNorm: one block per token ----------------
__global__ void ln_kernel(const float* __restrict__ x, const float* __restrict__ w,
                          const float* __restrict__ b, float* __restrict__ out) {
    int t = blockIdx.x, tid = threadIdx.x;
    const float* row = x + t * HDIM;
    __shared__ float red[256];

    float s = 0.f;
    for (int i = tid; i < HDIM; i += 256) s += row[i];
    red[tid] = s; __syncthreads();
    for (int off = 128; off > 0; off >>= 1) { if (tid < off) red[tid] += red[tid + off]; __syncthreads(); }
    float mu = red[0] * (1.f / HDIM);
    __syncthreads();

    float v = 0.f;
    for (int i = tid; i < HDIM; i += 256) { float d = row[i] - mu; v += d * d; }
    red[tid] = v; __syncthreads();
    for (int off = 128; off > 0; off >>= 1) { if (tid < off) red[tid] += red[tid + off]; __syncthreads(); }
    float rs = rsqrtf(red[0] * (1.f / HDIM) + 1e-5f);

    for (int i = tid; i < HDIM; i += 256)
        out[t * HDIM + i] = (row[i] - mu) * rs * w[i] + b[i];
}

// ---------------- generic fp32 GEMM: C[M,N] = A[M,K] * B[N,K]^T (+bias +resid) ----------------
__global__ void gemm_tn_kernel(const float* __restrict__ A, const float* __restrict__ Bm,
                               const float* __restrict__ bias, const float* __restrict__ resid,
                               float* __restrict__ C, int M, int N, int K) {
    __shared__ float As[16][64];
    __shared__ float Bs[16][64];
    int tid = threadIdx.x;
    int m0 = blockIdx.y * 64, n0 = blockIdx.x * 64;
    int am = tid >> 2, ak = (tid & 3) << 2;
    int tx = tid & 15, ty = tid >> 4;
    float acc[4][4] = {};

    const float* Ap = A  + (long)(m0 + am) * K + ak;
    const float* Bp = Bm + (long)(n0 + am) * K + ak;

    for (int k0 = 0; k0 < K; k0 += 16) {
        float4 a = *(const float4*)(Ap + k0);
        float4 b = *(const float4*)(Bp + k0);
        As[ak+0][am] = a.x; As[ak+1][am] = a.y; As[ak+2][am] = a.z; As[ak+3][am] = a.w;
        Bs[ak+0][am] = b.x; Bs[ak+1][am] = b.y; Bs[ak+2][am] = b.z; Bs[ak+3][am] = b.w;
        __syncthreads();
        #pragma unroll
        for (int k = 0; k < 16; k++) {
            float4 av = *(const float4*)&As[k][ty << 2];
            float4 bv = *(const float4*)&Bs[k][tx << 2];
            float aa[4] = {av.x, av.y, av.z, av.w};
            float bb[4] = {bv.x, bv.y, bv.z, bv.w};
            #pragma unroll
            for (int i = 0; i < 4; i++)
                #pragma unroll
                for (int j = 0; j < 4; j++)
                    acc[i][j] += aa[i] * bb[j];
        }
        __syncthreads();
    }

    #pragma unroll
    for (int i = 0; i < 4; i++) {
        int m = m0 + (ty << 2) + i;
        #pragma unroll
        for (int j = 0; j < 4; j++) {
            int n = n0 + (tx << 2) + j;
            float v = acc[i][j];
            if (bias)  v += bias[n];
            if (resid) v += resid[(long)m * N + n];
            C[(long)m * N + n] = v;
        }
    }
}

// ---------------- flash attention: 128 queries/block, q & o in registers ----------------
// dyn smem: Ks[64*64] | Vs[64*64] | Ps[128*65] = (4096+4096+8320)*4 = 66048 bytes
__global__ __launch_bounds__(128) void attn_kernel(const float* __restrict__ qkv,
                                                   float* __restrict__ aout) {
    extern __shared__ float sm[];
    float* Ks = sm;
    float* Vs = sm + 4096;
    float* Ps = sm + 8192;

    int h = blockIdx.y;
    int m0 = blockIdx.x * 128;
    int tid = threadIdx.x;
    int qrow = m0 + tid;

    float4 q[16], o[16];
    {
        const float4* qp = (const float4*)&qkv[(long)qrow * 3 * HDIM + h * HEADD];
        #pragma unroll
        for (int i = 0; i < 16; i++) { q[i] = qp[i]; o[i] = make_float4(0.f, 0.f, 0.f, 0.f); }
    }
    float mx = -1e30f, l = 0.f;

    int njt = 2 * blockIdx.x + 2;       // KV tiles of 64 needed for causal coverage
    for (int j = 0; j < njt; j++) {
        int n0 = j * 64;
        __syncthreads();
        #pragma unroll
        for (int i = 0; i < 8; i++) {   // 1024 float4 per tile / 128 threads
            int q4 = tid + i * 128;
            int r = q4 >> 4, d4 = q4 & 15;
            long gb = (long)(n0 + r) * 3 * HDIM + h * HEADD + d4 * 4;
            ((float4*)Ks)[q4] = *(const float4*)&qkv[gb + HDIM];
            ((float4*)Vs)[q4] = *(const float4*)&qkv[gb + 2 * HDIM];
        }
        __syncthreads();

        float tmax = mx;
        for (int c = 0; c < 64; c++) {
            const float4* kr = (const float4*)&Ks[c * 64];
            float s = 0.f;
            #pragma unroll
            for (int d = 0; d < 16; d++) {
                float4 kv = kr[d];
                s += q[d].x * kv.x + q[d].y * kv.y + q[d].z * kv.z + q[d].w * kv.w;
            }
            s *= 0.125f;                      // 1/sqrt(64)
            if (n0 + c > qrow) s = -1e30f;    // causal
            Ps[tid * 65 + c] = s;
            tmax = fmaxf(tmax, s);
        }
        float scale = __expf(mx - tmax);
        l *= scale;
        #pragma unroll
        for (int d = 0; d < 16; d++) {
            o[d].x *= scale; o[d].y *= scale; o[d].z *= scale; o[d].w *= scale;
        }
        for (int c = 0; c < 64; c++) {
            float p = __expf(Ps[tid * 65 + c] - tmax);
            l += p;
            Ps[tid * 65 + c] = p;
        }
        mx = tmax;
        for (int c = 0; c < 64; c++) {
            float p = Ps[tid * 65 + c];
            const float4* vr = (const float4*)&Vs[c * 64];
            #pragma unroll
            for (int d = 0; d < 16; d++) {
                float4 vv = vr[d];
                o[d].x += p * vv.x; o[d].y += p * vv.y; o[d].z += p * vv.z; o[d].w += p * vv.w;
            }
        }
    }

    float inv = 1.f / l;
    float4* op = (float4*)&aout[(long)qrow * HDIM + h * HEADD];
    #pragma unroll
    for (int d = 0; d < 16; d++) {
        float4 v = o[d];
        v.x *= inv; v.y *= inv; v.z *= inv; v.w *= inv;
        op[d] = v;
    }
}

// ---------------- router logits (fp32, exact — routing must match reference) ----------------
__global__ void router_kernel(const float* __restrict__ rw) {
    int t = blockIdx.x;
    int e = threadIdx.x >> 5, lane = threadIdx.x & 31;
    float s = 0.f;
    for (int i = lane; i < HDIM; i += 32)
        s += g_hn2[(long)t * HDIM + i] * rw[(long)e * HDIM + i];
    #pragma unroll
    for (int off = 16; off > 0; off >>= 1) s += __shfl_down_sync(0xffffffffu, s, off);
    if (lane == 0) g_logits[t * NEXP + e] = s;
}

// ---------------- softmax + top-2 per token ----------------
__global__ void top2_kernel() {
    int t = blockIdx.x * blockDim.x + threadIdx.x;
    if (t >= TS) return;
    float l[NEXP];
    float m = -1e30f;
    #pragma unroll
    for (int e = 0; e < NEXP; e++) { l[e] = g_logits[t * NEXP + e]; m = fmaxf(m, l[e]); }
    float sum = 0.f;
    #pragma unroll
    for (int e = 0; e < NEXP; e++) { l[e] = __expf(l[e] - m); sum += l[e]; }
    int i1 = 0;
    #pragma unroll
    for (int e = 1; e < NEXP; e++) if (l[e] > l[i1]) i1 = e;
    int i2 = (i1 == 0) ? 1 : 0;
    #pragma unroll
    for (int e = 0; e < NEXP; e++) if (e != i1 && l[e] > l[i2]) i2 = e;
    float inv = 1.f / sum;
    g_topi[2*t]   = i1;  g_gate[2*t]   = l[i1] * inv;
    g_topi[2*t+1] = i2;  g_gate[2*t+1] = l[i2] * inv;
}

// ---------------- deterministic per-expert token lists (block scan, no atomics) ----------------
__global__ void build_lists_kernel() {
    int e = blockIdx.x, tid = threadIdx.x;
    __shared__ int sc[256];
    __shared__ int sbase;
    if (tid == 0) sbase = 0;
    __syncthreads();
    for (int t0 = 0; t0 < TS; t0 += 256) {
        int t = t0 + tid;
        int flag = 0; float g = 0.f;
        int i0 = g_topi[2*t], i1 = g_topi[2*t+1];
        if (i0 == e)      { flag = 1; g = g_gate[2*t]; }
        else if (i1 == e) { flag = 1; g = g_gate[2*t+1]; }
        sc[tid] = flag;
        __syncthreads();
        for (int off = 1; off < 256; off <<= 1) {
            int v = (tid >= off) ? sc[tid - off] : 0;
            __syncthreads();
            sc[tid] += v;
            __syncthreads();
        }
        if (flag) {
            int pos = sbase + sc[tid] - 1;
            g_etok [e * TS + pos] = t;
            g_egate[e * TS + pos] = g;
        }
        __syncthreads();
        if (tid == 0) sbase += sc[255];
        __syncthreads();
    }
    if (tid == 0) g_cnt[e] = sbase;
}

// ---------------- exclusive scan of expert counts -> g_off ----------------
__global__ void scan_offsets_kernel() {
    if (threadIdx.x == 0) {
        int acc = 0;
        for (int e = 0; e < NEXP; e++) { g_off[e] = acc; acc += g_cnt[e]; }
    }
}

// ---------------- out = x1 (residual base for MoE scatter-add) ----------------
__global__ void copy_kernel(float* __restrict__ out) {
    int i = blockIdx.x * blockDim.x + threadIdx.x;
    out[i] = g_x1[i];
}

// ================= tf32 mma.sync helpers =================
__device__ __forceinline__ uint32_t f2tf32(float f) {
    uint32_t u;
    asm("cvt.rna.tf32.f32 %0, %1;" : "=r"(u) : "f"(f));
    return u;
}
__device__ __forceinline__ void mma_tf32(float* c, const uint32_t* a, const uint32_t* b) {
    asm volatile("mma.sync.aligned.m16n8k8.row.col.f32.tf32.tf32.f32 "
        "{%0,%1,%2,%3}, {%4,%5,%6,%7}, {%8,%9}, {%0,%1,%2,%3};"
        : "+f"(c[0]), "+f"(c[1]), "+f"(c[2]), "+f"(c[3])
        : "r"(a[0]), "r"(a[1]), "r"(a[2]), "r"(a[3]), "r"(b[0]), "r"(b[1]));
}

// fragment-order smem: aF[mt][ks][reg][lane], bF[nt][ks][reg][lane]
// A element (r,c) of a 16x8 tile: reg=(r>=8)+2*(c>=4), lane=(r&7)*4+(c&3)
// B element (k,n) of a 8x8 tile:  reg=k>>2,            lane=n*4+(k&3)
// C regs: row=g+(r>>1)*8, col=tg*2+(r&1)  with g=lane>>2, tg=lane&3

// ---------------- MoE GEMM1 (tf32): hmid[off[e]+m,:] = gelu( hn2[tok] @ w1[e] ) ----------------
// w1[e] is [K=HDIM][N=FF] row-major (n contiguous)
__global__ __launch_bounds__(128) void moe_gemm1_tf32(const float* __restrict__ w1) {
    int e = blockIdx.z;
    int cnt = g_cnt[e];
    int m0 = blockIdx.y * 64;
    if (m0 >= cnt) return;
    int base = g_off[e];
    int n0 = blockIdx.x * 64;

    __shared__ uint32_t aF[4][2][4][32];
    __shared__ uint32_t bF[8][2][2][32];
    __shared__ int toks[64];

    int tid = threadIdx.x;
    int lane = tid & 31, warp = tid >> 5;
    int wm = warp >> 1, wn = warp & 1;

    if (tid < 64) {
        int m = m0 + tid;
        toks[tid] = g_etok[e * TS + (m < cnt ? m : cnt - 1)];
    }
    __syncthreads();

    int lm = tid & 63;                 // A loader row
    int lj0 = (tid >> 6) * 2;          // A loader float4 idx
    int lr = lm & 15, lmt = lm >> 4;
    int bkr = tid >> 3;                // B loader k row
    int bn40 = (tid & 7) * 2;          // B loader float4 col idx

    float acc[2][4][4];
    #pragma unroll
    for (int i = 0; i < 2; i++)
        #pragma unroll
        for (int jn = 0; jn < 4; jn++)
            #pragma unroll
            for (int r = 0; r < 4; r++) acc[i][jn][r] = 0.f;

    const float* Bg = w1 + (long)e * HDIM * FF;
    long arow = (long)toks[lm] * HDIM;

    for (int k0 = 0; k0 < HDIM; k0 += 16) {
        #pragma unroll
        for (int t = 0; t < 2; t++) {
            int lj = lj0 + t;
            float4 a = *(const float4*)&g_hn2[arow + k0 + lj * 4];
            int ks = lj >> 1;
            int reg = (lr >> 3) + 2 * (lj & 1);
            uint32_t* dst = &aF[lmt][ks][reg][(lr & 7) * 4];
            dst[0] = f2tf32(a.x); dst[1] = f2tf32(a.y);
            dst[2] = f2tf32(a.z); dst[3] = f2tf32(a.w);
        }
        #pragma unroll
        for (int t = 0; t < 2; t++) {
            int n4 = bn40 + t;
            float4 b = *(const float4*)&Bg[(long)(k0 + bkr) * FF + n0 + n4 * 4];
            int ks = bkr >> 3, kc = bkr & 7;
            int tg = kc & 3, reg = kc >> 2;
            int nt = n4 >> 1;
            int g0 = (n4 & 1) * 4;
            bF[nt][ks][reg][(g0 + 0) * 4 + tg] = f2tf32(b.x);
            bF[nt][ks][reg][(g0 + 1) * 4 + tg] = f2tf32(b.y);
            bF[nt][ks][reg][(g0 + 2) * 4 + tg] = f2tf32(b.z);
            bF[nt][ks][reg][(g0 + 3) * 4 + tg] = f2tf32(b.w);
        }
        __syncthreads();
        #pragma unroll
        for (int ks = 0; ks < 2; ks++) {
            uint32_t afr[2][4], bfr[4][2];
            #pragma unroll
            for (int mt = 0; mt < 2; mt++)
                #pragma unroll
                for (int r = 0; r < 4; r++) afr[mt][r] = aF[wm * 2 + mt][ks][r][lane];
            #pragma unroll
            for (int nt = 0; nt < 4; nt++)
                #pragma unroll
                for (int r = 0; r < 2; r++) bfr[nt][r] = bF[wn * 4 + nt][ks][r][lane];
            #pragma unroll
            for (int mt = 0; mt < 2; mt++)
                #pragma unroll
                for (int nt = 0; nt < 4; nt++)
                    mma_tf32(acc[mt][nt], afr[mt], bfr[nt]);
        }
        __syncthreads();
    }

    int g = lane >> 2, tg = lane & 3;
    #pragma unroll
    for (int mt = 0; mt < 2; mt++)
        #pragma unroll
        for (int nt = 0; nt < 4; nt++)
            #pragma unroll
            for (int r = 0; r < 4; r++) {
                int row = wm * 32 + mt * 16 + g + (r >> 1) * 8;
                int col = wn * 32 + nt * 8 + tg * 2 + (r & 1);
                if (m0 + row < cnt) {
                    float v = acc[mt][nt][r];
                    float gl = 0.5f * v * (1.f + erff(v * 0.70710678118654752f));
                    g_hmid[(long)(base + m0 + row) * FF + n0 + col] = gl;
                }
            }
}

// ---------------- MoE GEMM2 (tf32): out[tok] += gate * ( hmid @ w2[e] ) ----------------
// w2[e] is [K=FF][N=HDIM] row-major (n contiguous)
__global__ __launch_bounds__(128) void moe_gemm2_tf32(const float* __restrict__ w2,
                                                      float* __restrict__ out) {
    int e = blockIdx.z;
    int cnt = g_cnt[e];
    int m0 = blockIdx.y * 64;
    if (m0 >= cnt) return;
    int base = g_off[e];
    int n0 = blockIdx.x * 64;

    __shared__ uint32_t aF[4][2][4][32];
    __shared__ uint32_t bF[8][2][2][32];
    __shared__ int   toks[64];
    __shared__ float gts[64];

    int tid = threadIdx.x;
    int lane = tid & 31, warp = tid >> 5;
    int wm = warp >> 1, wn = warp & 1;

    if (tid < 64) {
        int m = m0 + tid;
        int mc = (m < cnt ? m : cnt - 1);
        toks[tid] = g_etok [e * TS + mc];
        gts [tid] = g_egate[e * TS + mc];
    }
    __syncthreads();

    int lm = tid & 63;
    int lj0 = (tid >> 6) * 2;
    int lr = lm & 15, lmt = lm >> 4;
    int bkr = tid >> 3;
    int bn40 = (tid & 7) * 2;

    float acc[2][4][4];
    #pragma unroll
    for (int i = 0; i < 2; i++)
        #pragma unroll
        for (int jn = 0; jn < 4; jn++)
            #pragma unroll
            for (int r = 0; r < 4; r++) acc[i][jn][r] = 0.f;

    const float* Bg = w2 + (long)e * FF * HDIM;
    int lmrow = m0 + lm; if (lmrow >= cnt) lmrow = cnt - 1;   // clamp: no OOB, rows masked at store
    long arow = (long)(base + lmrow) * FF;

    for (int k0 = 0; k0 < FF; k0 += 16) {
        #pragma unroll
        for (int t = 0; t < 2; t++) {
            int lj = lj0 + t;
            float4 a = *(const float4*)&g_hmid[arow + k0 + lj * 4];
            int ks = lj >> 1;
            int reg = (lr >> 3) + 2 * (lj & 1);
            uint32_t* dst = &aF[lmt][ks][reg][(lr & 7) * 4];
            dst[0] = f2tf32(a.x); dst[1] = f2tf32(a.y);
            dst[2] = f2tf32(a.z); dst[3] = f2tf32(a.w);
        }
        #pragma unroll
        for (int t = 0; t < 2; t++) {
            int n4 = bn40 + t;
            float4 b = *(const float4*)&Bg[(long)(k0 + bkr) * HDIM + n0 + n4 * 4];
            int ks = bkr >> 3, kc = bkr & 7;
            int tg = kc & 3, reg = kc >> 2;
            int nt = n4 >> 1;
            int g0 = (n4 & 1) * 4;
            bF[nt][ks][reg][(g0 + 0) * 4 + tg] = f2tf32(b.x);
            bF[nt][ks][reg][(g0 + 1) * 4 + tg] = f2tf32(b.y);
            bF[nt][ks][reg][(g0 + 2) * 4 + tg] = f2tf32(b.z);
            bF[nt][ks][reg][(g0 + 3) * 4 + tg] = f2tf32(b.w);
        }
        __syncthreads();
        #pragma unroll
        for (int ks = 0; ks < 2; ks++) {
            uint32_t afr[2][4], bfr[4][2];
            #pragma unroll
            for (int mt = 0; mt < 2; mt++)
                #pragma unroll
                for (int r = 0; r < 4; r++) afr[mt][r] = aF[wm * 2 + mt][ks][r][lane];
            #pragma unroll
            for (int nt = 0; nt < 4; nt++)
                #pragma unroll
                for (int r = 0; r < 2; r++) bfr[nt][r] = bF[wn * 4 + nt][ks][r][lane];
            #pragma unroll
            for (int mt = 0; mt < 2; mt++)
                #pragma unroll
                for (int nt = 0; nt < 4; nt++)
                    mma_tf32(acc[mt][nt], afr[mt], bfr[nt]);
        }
        __syncthreads();
    }

    int g = lane >> 2, tg = lane & 3;
    #pragma unroll
    for (int mt = 0; mt < 2; mt++)
        #pragma unroll
        for (int nt = 0; nt < 4; nt++)
            #pragma unroll
            for (int r = 0; r < 4; r++) {
                int row = wm * 32 + mt * 16 + g + (r >> 1) * 8;
                int col = wn * 32 + nt * 8 + tg * 2 + (r & 1);
                if (m0 + row < cnt) {
                    int tok = toks[row];
                    float gg = gts[row];
                    atomicAdd(&out[(long)tok * HDIM + n0 + col], gg * acc[mt][nt][r]);
                }
            }
}

// ---------------- launch ----------------
extern "C" void kernel_launch(void* const* d_in, const int* in_sizes, int n_in,
                              void* d_out, int out_size) {
    const float* x    = (const float*)d_in[0];
    const float* ln1w = (const float*)d_in[1];
    const float* ln1b = (const float*)d_in[2];
    const float* wqkv = (const float*)d_in[3];
    const float* bqkv = (const float*)d_in[4];
    const float* wout = (const float*)d_in[5];
    const float* bout = (const float*)d_in[6];
    const float* ln2w = (const float*)d_in[7];
    const float* ln2b = (const float*)d_in[8];
    const float* rw   = (const float*)d_in[9];
    const float* w1   = (const float*)d_in[10];
    const float* w2   = (const float*)d_in[11];
    float* out = (float*)d_out;

    float *p_hn, *p_qkv, *p_attn, *p_x1, *p_hn2;
    cudaGetSymbolAddress((void**)&p_hn,   g_hn);
    cudaGetSymbolAddress((void**)&p_qkv,  g_qkv);
    cudaGetSymbolAddress((void**)&p_attn, g_attn);
    cudaGetSymbolAddress((void**)&p_x1,   g_x1);
    cudaGetSymbolAddress((void**)&p_hn2,  g_hn2);

    cudaFuncSetAttribute(attn_kernel, cudaFuncAttributeMaxDynamicSharedMemorySize, 66048);

    // 1) LN1
    ln_kernel<<<TS, 256>>>(x, ln1w, ln1b, p_hn);
    // 2) QKV projection (fp32 — routing-exact path)
    {
        dim3 g(3 * HDIM / 64, TS / 64);
        gemm_tn_kernel<<<g, 256>>>(p_hn, wqkv, bqkv, nullptr, p_qkv, TS, 3 * HDIM, HDIM);
    }
    // 3) causal attention (fp32)
    {
        dim3 g(TS / 128, NHEADS);
        attn_kernel<<<g, 128, 66048>>>(p_qkv, p_attn);
    }
    // 4) out projection + residual -> x1 (fp32)
    {
        dim3 g(HDIM / 64, TS / 64);
        gemm_tn_kernel<<<g, 256>>>(p_attn, wout, bout, x, p_x1, TS, HDIM, HDIM);
    }
    // 5) LN2
    ln_kernel<<<TS, 256>>>(p_x1, ln2w, ln2b, p_hn2);
    // 6) router + top-2 + deterministic expert lists + offsets
    router_kernel<<<TS, 256>>>(rw);
    top2_kernel<<<TS / 256, 256>>>();
    build_lists_kernel<<<NEXP, 256>>>();
    scan_offsets_kernel<<<1, 32>>>();
    // 7) out = x1
    copy_kernel<<<TS * HDIM / 256, 256>>>(out);
    // 8) MoE expert GEMMs (tf32 tensor cores, sparse top-2)
    {
        dim3 g1(FF / 64, TS / 64, NEXP);
        moe_gemm1_tf32<<<g1, 128>>>(w1);
        dim3 g2(HDIM / 64, TS / 64, NEXP);
        moe_gemm2_tf32<<<g2, 128>>>(w2, out);
    }
}